// round 1
// baseline (speedup 1.0000x reference)
#include <cuda_runtime.h>

// SSIM loss, fused. Exploits rank-2 structure of the reference "gaussian"
// window: K(i,j) = u(i) + u(j)  =>  conv = Vgauss(HBox) + VBox(HGauss).

#define KS 11
#define TILE 32
#define HROWS 42          // TILE + 10 halo rows
#define RAWW 42           // raw tile width (with halo)
#define RAWS 44           // raw row stride (padded)
#define HSTR 33           // H-plane row stride (padded)
#define HPLANE (HROWS*HSTR)   // 1386 floats per plane
#define NBLK 8192
#define IMG 512

__device__ float g_u[KS];
__device__ float g_part[NBLK];

// Recover separable component u(i) = g(i)/S from the rank-2 window:
// row sums R(i) = 11 u(i) + T/22 (T = total sum), so u(i) = (R(i)-T/22)/11.
__global__ void prep_kernel(const float* __restrict__ w) {
    if (threadIdx.x == 0) {
        float R[KS];
        float T = 0.f;
        #pragma unroll
        for (int i = 0; i < KS; i++) {
            float s = 0.f;
            #pragma unroll
            for (int j = 0; j < KS; j++) s += w[i*KS + j];
            R[i] = s; T += s;
        }
        float U = T * (1.f/22.f);
        #pragma unroll
        for (int i = 0; i < KS; i++) g_u[i] = (R[i] - U) * (1.f/11.f);
    }
}

extern __shared__ float smem[];

__global__ __launch_bounds__(256, 3)
void ssim_kernel(const float* __restrict__ img1, const float* __restrict__ img2) {
    float* sA = smem;                        // HROWS * RAWS
    float* sB = sA + HROWS*RAWS;             // HROWS * RAWS
    float* sH = sB + HROWS*RAWS;             // 10 planes * HPLANE

    const int tid = threadIdx.x;
    const int n  = blockIdx.z;
    const int x0 = blockIdx.x * TILE;
    const int y0 = blockIdx.y * TILE;
    const float* p1 = img1 + (size_t)n * IMG * IMG;
    const float* p2 = img2 + (size_t)n * IMG * IMG;

    float uu[KS];
    #pragma unroll
    for (int t = 0; t < KS; t++) uu[t] = g_u[t];

    // ---- Phase 1: stage raw tiles (with halo, zero-padded) ----
    for (int i = tid; i < HROWS*RAWW; i += 256) {
        int r = i / RAWW, c = i % RAWW;
        int gr = y0 - 5 + r, gc = x0 - 5 + c;
        float a = 0.f, b = 0.f;
        if (gr >= 0 && gr < IMG && gc >= 0 && gc < IMG) {
            int idx = gr*IMG + gc;
            a = p1[idx]; b = p2[idx];
        }
        sA[r*RAWS + c] = a;
        sB[r*RAWS + c] = b;
    }
    __syncthreads();

    // ---- Phase 2: horizontal pass. For 5 planes {a,b,a2,b2,ab} compute
    //      HBox (11-tap box) and HGauss (11-tap u-weighted) per halo row. ----
    for (int i = tid; i < HROWS*TILE; i += 256) {
        int r = i >> 5, c = i & 31;
        float hb0=0,hb1=0,hb2=0,hb3=0,hb4=0;
        float hg0=0,hg1=0,hg2=0,hg3=0,hg4=0;
        const float* ra = sA + r*RAWS + c;
        const float* rb = sB + r*RAWS + c;
        #pragma unroll
        for (int j = 0; j < KS; j++) {
            float a = ra[j];
            float b = rb[j];
            float aa = a*a, bb = b*b, ab = a*b;
            float u = uu[j];
            hb0 += a;    hg0 += u*a;
            hb1 += b;    hg1 += u*b;
            hb2 += aa;   hg2 += u*aa;
            hb3 += bb;   hg3 += u*bb;
            hb4 += ab;   hg4 += u*ab;
        }
        int o = r*HSTR + c;
        sH[0*HPLANE + o] = hb0;
        sH[1*HPLANE + o] = hb1;
        sH[2*HPLANE + o] = hb2;
        sH[3*HPLANE + o] = hb3;
        sH[4*HPLANE + o] = hb4;
        sH[5*HPLANE + o] = hg0;
        sH[6*HPLANE + o] = hg1;
        sH[7*HPLANE + o] = hg2;
        sH[8*HPLANE + o] = hg3;
        sH[9*HPLANE + o] = hg4;
    }
    __syncthreads();

    // ---- Phase 3: vertical pass + SSIM. Each thread: 1 column, 4 rows. ----
    const int tx = tid & 31;
    const int r0 = (tid >> 5) * 4;

    float cv[5][4];
    #pragma unroll
    for (int p = 0; p < 5; p++) {
        float vg[4] = {0.f, 0.f, 0.f, 0.f};
        float vb[4] = {0.f, 0.f, 0.f, 0.f};
        const float* HB = sH + p*HPLANE + r0*HSTR + tx;
        const float* HG = sH + (5+p)*HPLANE + r0*HSTR + tx;
        #pragma unroll
        for (int k = 0; k < 15; k++) {
            float hbv = HB[k*HSTR];
            float hgv = HG[k*HSTR];
            #pragma unroll
            for (int o = 0; o < 4; o++) {
                int t = k - o;
                if (t >= 0 && t < KS) {
                    vg[o] += uu[t] * hbv;
                    vb[o] += hgv;
                }
            }
        }
        #pragma unroll
        for (int o = 0; o < 4; o++) cv[p][o] = vg[o] + vb[o];
    }

    const float DR = 1603.64208984375f - 1396.9390869140625f;
    const float C1 = (0.01f*DR)*(0.01f*DR);
    const float C2 = (0.03f*DR)*(0.03f*DR);

    float lsum = 0.f;
    #pragma unroll
    for (int o = 0; o < 4; o++) {
        float mu1 = cv[0][o], mu2 = cv[1][o];
        float mu11 = mu1*mu1, mu22 = mu2*mu2, mu12 = mu1*mu2;
        float s11 = cv[2][o] - mu11;
        float s22 = cv[3][o] - mu22;
        float s12 = cv[4][o] - mu12;
        float num = (2.f*mu12 + C1) * (2.f*s12 + C2);
        float den = (mu11 + mu22 + C1) * (s11 + s22 + C2);
        lsum += num / den;
    }

    // ---- Block reduction (deterministic partials) ----
    #pragma unroll
    for (int off = 16; off; off >>= 1)
        lsum += __shfl_down_sync(0xffffffffu, lsum, off);
    if ((tid & 31) == 0) sA[tid >> 5] = lsum;   // sA reads are long done
    __syncthreads();
    if (tid == 0) {
        float s = 0.f;
        #pragma unroll
        for (int w = 0; w < 8; w++) s += sA[w];
        int bl = blockIdx.x + 16*blockIdx.y + 256*blockIdx.z;
        g_part[bl] = s;
    }
}

__global__ void finish_kernel(float* __restrict__ out) {
    __shared__ float sh[256];
    float s = 0.f;
    for (int i = threadIdx.x; i < NBLK; i += 256) s += g_part[i];
    sh[threadIdx.x] = s;
    __syncthreads();
    for (int k = 128; k; k >>= 1) {
        if (threadIdx.x < k) sh[threadIdx.x] += sh[threadIdx.x + k];
        __syncthreads();
    }
    if (threadIdx.x == 0)
        out[0] = sh[0] * (1.f / (32.f * 512.f * 512.f));
}

extern "C" void kernel_launch(void* const* d_in, const int* in_sizes, int n_in,
                              void* d_out, int out_size) {
    const float* preds  = (const float*)d_in[0];
    const float* target = (const float*)d_in[1];
    const float* window = (const float*)d_in[2];
    float* out = (float*)d_out;

    const int smem_bytes = (2*HROWS*RAWS + 10*HPLANE) * (int)sizeof(float); // 70224
    cudaFuncSetAttribute(ssim_kernel, cudaFuncAttributeMaxDynamicSharedMemorySize, smem_bytes);

    prep_kernel<<<1, 32>>>(window);
    dim3 grid(IMG/TILE, IMG/TILE, 32);
    ssim_kernel<<<grid, 256, smem_bytes>>>(preds, target);
    finish_kernel<<<1, 256>>>(out);
}

// round 2
// speedup vs baseline: 1.0722x; 1.0722x over previous
#include <cuda_runtime.h>

// SSIM loss, fused, f32x2-packed. Rank-2 window: K(i,j) = u(i) + u(j)
//   => conv = VGauss(HBox) + VBox(HGauss).

#define KS 11
#define TILE 32
#define HROWS 42          // TILE + 10 halo rows
#define RAWW 42           // raw tile width (with halo)
#define RAWS 44           // raw row stride (padded)
#define HSTR 33           // H-plane row stride (padded)
#define HPLANE (HROWS*HSTR)
#define NBLK 8192
#define IMG 512

__device__ float g_part[NBLK];

typedef unsigned long long u64;

__device__ __forceinline__ u64 f2pack(float lo, float hi) {
    u64 r; asm("mov.b64 %0, {%1, %2};" : "=l"(r) : "f"(lo), "f"(hi)); return r;
}
__device__ __forceinline__ void f2unpack(float& lo, float& hi, u64 v) {
    asm("mov.b64 {%0, %1}, %2;" : "=f"(lo), "=f"(hi) : "l"(v));
}
__device__ __forceinline__ u64 add2(u64 a, u64 b) {
    u64 d; asm("add.rn.f32x2 %0, %1, %2;" : "=l"(d) : "l"(a), "l"(b)); return d;
}
__device__ __forceinline__ u64 mul2(u64 a, u64 b) {
    u64 d; asm("mul.rn.f32x2 %0, %1, %2;" : "=l"(d) : "l"(a), "l"(b)); return d;
}
__device__ __forceinline__ u64 fma2(u64 a, u64 b, u64 c) {
    u64 d; asm("fma.rn.f32x2 %0, %1, %2, %3;" : "=l"(d) : "l"(a), "l"(b), "l"(c)); return d;
}

extern __shared__ float smem[];

__global__ __launch_bounds__(256, 3)
void ssim_kernel(const float* __restrict__ img1, const float* __restrict__ img2,
                 const float* __restrict__ win) {
    float* sA = smem;                        // HROWS * RAWS
    float* sB = sA + HROWS*RAWS;             // HROWS * RAWS
    float* sH = sB + HROWS*RAWS;             // 10 planes * HPLANE
    __shared__ float sR[16];

    const int tid = threadIdx.x;
    const int n  = blockIdx.z;
    const int x0 = blockIdx.x * TILE;
    const int y0 = blockIdx.y * TILE;
    const float* p1 = img1 + (size_t)n * IMG * IMG;
    const float* p2 = img2 + (size_t)n * IMG * IMG;

    // ---- Phase 0: row sums of window (for u recovery) ----
    if (tid < KS) {
        float s = 0.f;
        #pragma unroll
        for (int j = 0; j < KS; j++) s += win[tid*KS + j];
        sR[tid] = s;
    }

    // ---- Phase 1: stage raw tiles (with halo, zero-padded) ----
    for (int i = tid; i < HROWS*RAWW; i += 256) {
        int r = i / RAWW, c = i - r*RAWW;
        int gr = y0 - 5 + r, gc = x0 - 5 + c;
        float a = 0.f, b = 0.f;
        if (gr >= 0 && gr < IMG && gc >= 0 && gc < IMG) {
            int idx = gr*IMG + gc;
            a = p1[idx]; b = p2[idx];
        }
        sA[r*RAWS + c] = a;
        sB[r*RAWS + c] = b;
    }
    __syncthreads();

    // Recover u(i) = (R(i) - T/22)/11 per thread (registers).
    float uu[KS];
    {
        float T = 0.f;
        #pragma unroll
        for (int i = 0; i < KS; i++) T += sR[i];
        float U = T * (1.f/22.f);
        #pragma unroll
        for (int i = 0; i < KS; i++) uu[i] = (sR[i] - U) * (1.f/11.f);
    }

    // ---- Phase 2: horizontal pass, packed over column pairs (c, c+16).
    //      Per halo row: HBox (box) and HGauss (u-weighted), 5 stat planes. ----
    {
        u64 ug[KS];
        #pragma unroll
        for (int t = 0; t < KS; t++) ug[t] = f2pack(uu[t], uu[t]);

        for (int i = tid; i < HROWS*16; i += 256) {
            int r = i >> 4, c = i & 15;
            const float* ra = sA + r*RAWS + c;
            const float* rb = sB + r*RAWS + c;
            u64 hb0=0,hb1=0,hb2=0,hb3=0,hb4=0;
            u64 hg0=0,hg1=0,hg2=0,hg3=0,hg4=0;
            #pragma unroll
            for (int j = 0; j < KS; j++) {
                u64 a = f2pack(ra[j], ra[j+16]);
                u64 b = f2pack(rb[j], rb[j+16]);
                u64 aa = mul2(a,a);
                u64 bb = mul2(b,b);
                u64 ab = mul2(a,b);
                hb0 = add2(hb0,a);  hg0 = fma2(ug[j],a,hg0);
                hb1 = add2(hb1,b);  hg1 = fma2(ug[j],b,hg1);
                hb2 = add2(hb2,aa); hg2 = fma2(ug[j],aa,hg2);
                hb3 = add2(hb3,bb); hg3 = fma2(ug[j],bb,hg3);
                hb4 = add2(hb4,ab); hg4 = fma2(ug[j],ab,hg4);
            }
            int o = r*HSTR + c;
            float lo, hi;
            f2unpack(lo,hi,hb0); sH[0*HPLANE+o]=lo; sH[0*HPLANE+o+16]=hi;
            f2unpack(lo,hi,hb1); sH[1*HPLANE+o]=lo; sH[1*HPLANE+o+16]=hi;
            f2unpack(lo,hi,hb2); sH[2*HPLANE+o]=lo; sH[2*HPLANE+o+16]=hi;
            f2unpack(lo,hi,hb3); sH[3*HPLANE+o]=lo; sH[3*HPLANE+o+16]=hi;
            f2unpack(lo,hi,hb4); sH[4*HPLANE+o]=lo; sH[4*HPLANE+o+16]=hi;
            f2unpack(lo,hi,hg0); sH[5*HPLANE+o]=lo; sH[5*HPLANE+o+16]=hi;
            f2unpack(lo,hi,hg1); sH[6*HPLANE+o]=lo; sH[6*HPLANE+o+16]=hi;
            f2unpack(lo,hi,hg2); sH[7*HPLANE+o]=lo; sH[7*HPLANE+o+16]=hi;
            f2unpack(lo,hi,hg3); sH[8*HPLANE+o]=lo; sH[8*HPLANE+o+16]=hi;
            f2unpack(lo,hi,hg4); sH[9*HPLANE+o]=lo; sH[9*HPLANE+o+16]=hi;
        }
    }
    __syncthreads();

    // ---- Phase 3: vertical pass + SSIM. 1 column, 4 rows per thread.
    //      VBox via sliding window; VGauss direct. ----
    const int tx = tid & 31;
    const int r0 = (tid >> 5) * 4;

    float cv[5][4];
    #pragma unroll
    for (int p = 0; p < 5; p++) {
        // VBox of HGauss (sliding)
        float vb[4];
        {
            const float* HG = sH + (5+p)*HPLANE + r0*HSTR + tx;
            float hgv[15];
            #pragma unroll
            for (int k = 0; k < 15; k++) hgv[k] = HG[k*HSTR];
            float s = hgv[0];
            #pragma unroll
            for (int k = 1; k < 11; k++) s += hgv[k];
            vb[0] = s;
            vb[1] = vb[0] - hgv[0] + hgv[11];
            vb[2] = vb[1] - hgv[1] + hgv[12];
            vb[3] = vb[2] - hgv[2] + hgv[13];
        }
        // VGauss of HBox (direct 11-tap)
        float vg[4] = {0.f,0.f,0.f,0.f};
        {
            const float* HB = sH + p*HPLANE + r0*HSTR + tx;
            #pragma unroll
            for (int k = 0; k < 15; k++) {
                float hbv = HB[k*HSTR];
                #pragma unroll
                for (int o = 0; o < 4; o++) {
                    int t = k - o;
                    if (t >= 0 && t < KS) vg[o] += uu[t] * hbv;
                }
            }
        }
        #pragma unroll
        for (int o = 0; o < 4; o++) cv[p][o] = vg[o] + vb[o];
    }

    const float DR = 1603.64208984375f - 1396.9390869140625f;
    const float C1 = (0.01f*DR)*(0.01f*DR);
    const float C2 = (0.03f*DR)*(0.03f*DR);

    float lsum = 0.f;
    #pragma unroll
    for (int o = 0; o < 4; o++) {
        float mu1 = cv[0][o], mu2 = cv[1][o];
        float mu11 = mu1*mu1, mu22 = mu2*mu2, mu12 = mu1*mu2;
        float s11 = cv[2][o] - mu11;
        float s22 = cv[3][o] - mu22;
        float s12 = cv[4][o] - mu12;
        float num = (2.f*mu12 + C1) * (2.f*s12 + C2);
        float den = (mu11 + mu22 + C1) * (s11 + s22 + C2);
        lsum += __fdividef(num, den);
    }

    // ---- Block reduction (deterministic partials) ----
    #pragma unroll
    for (int off = 16; off; off >>= 1)
        lsum += __shfl_down_sync(0xffffffffu, lsum, off);
    if ((tid & 31) == 0) sA[tid >> 5] = lsum;   // sA no longer read
    __syncthreads();
    if (tid == 0) {
        float s = 0.f;
        #pragma unroll
        for (int w = 0; w < 8; w++) s += sA[w];
        int bl = blockIdx.x + 16*blockIdx.y + 256*blockIdx.z;
        g_part[bl] = s;
    }
}

__global__ void finish_kernel(float* __restrict__ out) {
    __shared__ float sh[256];
    float s = 0.f;
    for (int i = threadIdx.x; i < NBLK; i += 256) s += g_part[i];
    sh[threadIdx.x] = s;
    __syncthreads();
    for (int k = 128; k; k >>= 1) {
        if (threadIdx.x < k) sh[threadIdx.x] += sh[threadIdx.x + k];
        __syncthreads();
    }
    if (threadIdx.x == 0)
        out[0] = sh[0] * (1.f / (32.f * 512.f * 512.f));
}

extern "C" void kernel_launch(void* const* d_in, const int* in_sizes, int n_in,
                              void* d_out, int out_size) {
    const float* preds  = (const float*)d_in[0];
    const float* target = (const float*)d_in[1];
    const float* window = (const float*)d_in[2];
    float* out = (float*)d_out;

    const int smem_bytes = (2*HROWS*RAWS + 10*HPLANE) * (int)sizeof(float); // 70224
    cudaFuncSetAttribute(ssim_kernel, cudaFuncAttributeMaxDynamicSharedMemorySize, smem_bytes);

    dim3 grid(IMG/TILE, IMG/TILE, 32);
    ssim_kernel<<<grid, 256, smem_bytes>>>(preds, target, window);
    finish_kernel<<<1, 256>>>(out);
}